// round 5
// baseline (speedup 1.0000x reference)
#include <cuda_runtime.h>

#define NB 512                 // max resident blocks (148 SMs * 4/SM = 592 slots)
#define NT 256
#define NWARP 8
#define CHUNKS 32              // float4 chunks per tile
#define COLS_PER_TILE 128

__device__ float        g_partials[NB];
__device__ unsigned int g_bar;   // monotonic ticket counter (never reset)

__global__ void __launch_bounds__(NT, 4)
ril_fused_kernel(const float* __restrict__ x,
                 const float* __restrict__ weights,
                 const float* __restrict__ min_vals,
                 const float* __restrict__ max_vals,
                 const int* __restrict__ start_pos,
                 const int* __restrict__ offsets,
                 const int* __restrict__ sizes,
                 const int* __restrict__ out_mask,
                 float* __restrict__ out,
                 int B, int D, int G, int Wn, int OUTN, int total, int ntiles)
{
    extern __shared__ float4 sraw[];
    float4 (*sx)[CHUNKS] = (float4 (*)[CHUNKS])sraw;   // [NWARP][CHUNKS] = 4KB
    float* smv = (float*)(sraw + NWARP * CHUNKS);      // G floats

    const int lane = threadIdx.x & 31;
    const int w    = threadIdx.x >> 5;
    const float inv_b = 1.0f / (float)B;

    for (int i = threadIdx.x; i < G; i += NT) smv[i] = __ldg(&min_vals[i]);
    __syncthreads();

    // ---- Phase 1: grid-stride over 128-column tiles ----
    float acc = 0.0f;
    for (int tile = blockIdx.x; tile < ntiles; tile += gridDim.x) {
        // Row-load: warp w accumulates rows w, w+8, ... for its float4 chunk
        const int chunk = tile * CHUNKS + lane;
        float4 a4 = make_float4(0.f, 0.f, 0.f, 0.f);
        if (chunk * 4 + 3 < D) {
            for (int b = w; b < B; b += NWARP) {
                const float4 xv = __ldg((const float4*)(x + (size_t)b * D) + chunk);
                a4.x += xv.x; a4.y += xv.y; a4.z += xv.z; a4.w += xv.w;
            }
        } else if (chunk * 4 < D) {
            float tmp[4] = {0.f, 0.f, 0.f, 0.f};
            for (int b = w; b < B; b += NWARP)
                for (int k = 0; k < 4; ++k)
                    if (chunk * 4 + k < D) tmp[k] += x[(size_t)b * D + chunk * 4 + k];
            a4.x = tmp[0]; a4.y = tmp[1]; a4.z = tmp[2]; a4.w = tmp[3];
        }
        sx[w][lane] = a4;
        __syncthreads();

        // Compute: threads 0..127, one scalar column each
        const int col = tile * COLS_PER_TILE + threadIdx.x;
        if (threadIdx.x < COLS_PER_TILE && col < D) {
            const int c_chunk = threadIdx.x >> 2;
            const int c_comp  = threadIdx.x & 3;
            float s = 0.0f;
            #pragma unroll
            for (int ww = 0; ww < NWARP; ++ww) {
                const float* p = (const float*)&sx[ww][c_chunk];
                s += p[c_comp];
            }
            const float vv = s * inv_b;

            int lo = 0, hi = G;
            while (lo < hi) {
                int mid = (lo + hi) >> 1;
                if (smv[mid] <= vv) lo = mid + 1; else hi = mid;
            }
            int g  = lo - 1;
            int gc = min(max(g, 0), G - 1);
            bool in_range = (g >= 0) && (vv >= smv[gc]) && (vv <= __ldg(&max_vals[gc]));
            int pos = col - __ldg(&start_pos[gc]);
            bool valid = in_range && (pos >= 0) && (pos < __ldg(&sizes[gc]));
            int widx = __ldg(&offsets[gc]) + pos;
            widx = min(max(widx, 0), Wn - 1);
            float wv = valid ? __ldg(&weights[widx]) : 0.0f;
            acc += vv * wv;
        }
        __syncthreads();   // protect sx before next tile overwrites it
    }

    // Block reduce
    #pragma unroll
    for (int o = 16; o > 0; o >>= 1)
        acc += __shfl_down_sync(0xffffffffu, acc, o);
    __shared__ float red[NWARP];
    if (lane == 0) red[w] = acc;
    __syncthreads();
    if (threadIdx.x == 0) {
        float p = 0.0f;
        #pragma unroll
        for (int k = 0; k < NWARP; ++k) p += red[k];
        g_partials[blockIdx.x] = p;
    }

    // ---- Device-wide ticket barrier (monotonic; survives graph replays) ----
    if (threadIdx.x == 0) {
        __threadfence();
        unsigned int arrival = atomicAdd(&g_bar, 1u) + 1u;
        unsigned int target  = ((arrival - 1u) / gridDim.x + 1u) * gridDim.x;
        unsigned int c;
        do {
            asm volatile("ld.acquire.gpu.u32 %0, [%1];" : "=r"(c) : "l"(&g_bar));
        } while (c < target);
    }
    __syncthreads();

    // ---- Phase 2: every block sums partials in a fixed deterministic tree ----
    float a2 = 0.0f;
    for (int i = threadIdx.x; i < (int)gridDim.x; i += NT)
        a2 += *(volatile float*)&g_partials[i];
    #pragma unroll
    for (int o = 16; o > 0; o >>= 1)
        a2 += __shfl_down_sync(0xffffffffu, a2, o);
    __shared__ float red2[NWARP];
    __shared__ float s_val;
    if (lane == 0) red2[w] = a2;
    __syncthreads();
    if (threadIdx.x == 0) {
        float s = 0.0f;
        #pragma unroll
        for (int k = 0; k < NWARP; ++k) s += red2[k];
        s_val = s;
    }
    __syncthreads();
    const float s = s_val;

    // ---- Output: each block writes its contiguous slice ----
    const int per = (total + (int)gridDim.x - 1) / (int)gridDim.x;
    const int j0  = blockIdx.x * per;
    const int j1  = min(j0 + per, total);
    for (int j = j0 + threadIdx.x; j < j1; j += NT) {
        float o = 0.0f;
        if (j < OUTN) o = (__ldg(&out_mask[j]) != 0) ? s : 0.0f;
        out[j] = o;
    }
}

extern "C" void kernel_launch(void* const* d_in, const int* in_sizes, int n_in,
                              void* d_out, int out_size)
{
    const float* x        = (const float*)d_in[0];
    const float* weights  = (const float*)d_in[1];
    const float* min_vals = (const float*)d_in[2];
    const float* max_vals = (const float*)d_in[3];
    const int*   start_p  = (const int*)d_in[4];
    const int*   offsets  = (const int*)d_in[5];
    const int*   sizes    = (const int*)d_in[6];
    const int*   out_mask = (const int*)d_in[7];
    float* out = (float*)d_out;

    int G  = in_sizes[2];
    int Wn = in_sizes[1];
    int D  = Wn / G;
    int B  = in_sizes[0] / D;
    int OUTN = in_sizes[7];

    int ntiles = (D + COLS_PER_TILE - 1) / COLS_PER_TILE;  // 512 for D=65536
    int blocks = ntiles < NB ? ntiles : NB;                // grid never exceeds resident capacity
    size_t shmem = NWARP * CHUNKS * sizeof(float4) + (size_t)G * sizeof(float);

    ril_fused_kernel<<<blocks, NT, shmem>>>(
        x, weights, min_vals, max_vals, start_p, offsets, sizes,
        out_mask, out, B, D, G, Wn, OUTN, out_size, ntiles);
}

// round 6
// speedup vs baseline: 1.1047x; 1.1047x over previous
#include <cuda_runtime.h>

#define NB 256                 // blocks; launch_bounds(256,2) -> 296 resident slots >= 256
#define NT 256

__device__ float        g_partials[NB];
__device__ unsigned int g_bar;   // monotonic ticket counter (never reset)

__global__ void __launch_bounds__(NT, 2)
ril_fused_kernel(const float* __restrict__ x,
                 const float* __restrict__ weights,
                 const float* __restrict__ min_vals,
                 const float* __restrict__ max_vals,
                 const int* __restrict__ start_pos,
                 const int* __restrict__ offsets,
                 const int* __restrict__ sizes,
                 const int* __restrict__ out_mask,
                 float* __restrict__ out,
                 int B, int D, int G, int Wn, int OUTN, int total)
{
    extern __shared__ float smv[];  // G floats: min_vals

    const int lane = threadIdx.x & 31;
    const int w    = threadIdx.x >> 5;
    const float inv_b = 1.0f / (float)B;

    for (int i = threadIdx.x; i < G; i += NT) smv[i] = __ldg(&min_vals[i]);
    __syncthreads();

    // ---- Phase 1: one column per thread, grid-stride for generality ----
    float acc = 0.0f;
    const int stride = (int)gridDim.x * NT;
    for (int col = blockIdx.x * NT + threadIdx.x; col < D; col += stride) {
        // 8 independent coalesced row loads (MLP = B)
        float s = 0.0f;
        #pragma unroll 8
        for (int b = 0; b < B; ++b)
            s += __ldg(x + (size_t)b * D + col);
        const float vv = s * inv_b;

        // searchsorted(min_vals, v, 'right') - 1
        int lo = 0, hi = G;
        while (lo < hi) {
            int mid = (lo + hi) >> 1;
            if (smv[mid] <= vv) lo = mid + 1; else hi = mid;
        }
        int g  = lo - 1;
        int gc = min(max(g, 0), G - 1);
        bool in_range = (g >= 0) && (vv >= smv[gc]) && (vv <= __ldg(&max_vals[gc]));
        int pos = col - __ldg(&start_pos[gc]);
        bool valid = in_range && (pos >= 0) && (pos < __ldg(&sizes[gc]));
        int widx = __ldg(&offsets[gc]) + pos;
        widx = min(max(widx, 0), Wn - 1);
        float wv = valid ? __ldg(&weights[widx]) : 0.0f;
        acc += vv * wv;
    }

    // ---- Block reduce ----
    #pragma unroll
    for (int o = 16; o > 0; o >>= 1)
        acc += __shfl_down_sync(0xffffffffu, acc, o);
    __shared__ float red[NT / 32];
    if (lane == 0) red[w] = acc;
    __syncthreads();
    if (threadIdx.x == 0) {
        float p = 0.0f;
        #pragma unroll
        for (int k = 0; k < NT / 32; ++k) p += red[k];
        g_partials[blockIdx.x] = p;
    }

    // ---- Device-wide ticket barrier (monotonic; survives graph replays) ----
    if (threadIdx.x == 0) {
        __threadfence();
        unsigned int arrival = atomicAdd(&g_bar, 1u) + 1u;
        unsigned int target  = ((arrival - 1u) / gridDim.x + 1u) * gridDim.x;
        unsigned int c;
        do {
            asm volatile("ld.acquire.gpu.u32 %0, [%1];" : "=r"(c) : "l"(&g_bar));
        } while (c < target);
    }
    __syncthreads();

    // ---- Phase 2: all blocks sum partials with a fixed deterministic tree ----
    float a2 = 0.0f;
    for (int i = threadIdx.x; i < (int)gridDim.x; i += NT)
        a2 += *(volatile float*)&g_partials[i];
    #pragma unroll
    for (int o = 16; o > 0; o >>= 1)
        a2 += __shfl_down_sync(0xffffffffu, a2, o);
    __shared__ float red2[NT / 32];
    __shared__ float s_val;
    if (lane == 0) red2[w] = a2;
    __syncthreads();
    if (threadIdx.x == 0) {
        float s = 0.0f;
        #pragma unroll
        for (int k = 0; k < NT / 32; ++k) s += red2[k];
        s_val = s;
    }
    __syncthreads();
    const float s = s_val;

    // ---- Output: each block writes its contiguous slice, vectorized ----
    const int per = (total + (int)gridDim.x - 1) / (int)gridDim.x;
    const int j0  = blockIdx.x * per;
    const int j1  = min(j0 + per, total);

    if ((j0 & 3) == 0 && (per & 3) == 0 && (OUTN & 3) == 0) {
        // vector path: 4 floats per store
        for (int j = j0 + threadIdx.x * 4; j < j1; j += NT * 4) {
            float4 o4 = make_float4(0.f, 0.f, 0.f, 0.f);
            if (j + 3 < OUTN) {
                const int4 m4 = __ldg((const int4*)(out_mask + j));
                o4.x = m4.x ? s : 0.0f;
                o4.y = m4.y ? s : 0.0f;
                o4.z = m4.z ? s : 0.0f;
                o4.w = m4.w ? s : 0.0f;
            }
            *(float4*)(out + j) = o4;
        }
    } else {
        for (int j = j0 + threadIdx.x; j < j1; j += NT) {
            float o = 0.0f;
            if (j < OUTN) o = (__ldg(&out_mask[j]) != 0) ? s : 0.0f;
            out[j] = o;
        }
    }
}

extern "C" void kernel_launch(void* const* d_in, const int* in_sizes, int n_in,
                              void* d_out, int out_size)
{
    const float* x        = (const float*)d_in[0];
    const float* weights  = (const float*)d_in[1];
    const float* min_vals = (const float*)d_in[2];
    const float* max_vals = (const float*)d_in[3];
    const int*   start_p  = (const int*)d_in[4];
    const int*   offsets  = (const int*)d_in[5];
    const int*   sizes    = (const int*)d_in[6];
    const int*   out_mask = (const int*)d_in[7];
    float* out = (float*)d_out;

    int G  = in_sizes[2];
    int Wn = in_sizes[1];
    int D  = Wn / G;
    int B  = in_sizes[0] / D;
    int OUTN = in_sizes[7];

    size_t shmem = (size_t)G * sizeof(float);
    ril_fused_kernel<<<NB, NT, shmem>>>(
        x, weights, min_vals, max_vals, start_p, offsets, sizes,
        out_mask, out, B, D, G, Wn, OUTN, out_size);
}